// round 15
// baseline (speedup 1.0000x reference)
#include <cuda_runtime.h>
#include <cuda_fp16.h>
#include <math.h>
#include <stdint.h>

#define NN 50000
#define EE 400000
#define GG 64

// ---------------- scratch ----------------
__device__ uint16_t g_Y[NN * 384];      // aggregated weighted features, fp16, (c,h)-interleaved
__device__ uint16_t g_xh[NN * 96];      // fp16 copy of current features
__device__ float4   g_B4[NN * 24];      // N x 96 features
__device__ float4   g_C4[NN * 24];      // N x 96 / N x 64
__device__ float4   g_ealpha[NN];
__device__ float    g_v[3][404];        // per-layer projected attention vectors
__device__ float    g_pooled[GG * 64];
__device__ float    g_W2[3][384 * 96];  // per-layer stacked+permuted+scaled message weights
__device__ float    g_bavg[3][96];      // per-layer 0.25*sum_h bm_h
__device__ int      g_deg[NN];
__device__ int      g_rowptr[NN + 1];
__device__ int      g_wrk[NN];
__device__ int      g_colsrc[EE];
__device__ int      g_partials[128];

// side streams + events, created once at load (no device memory involved)
struct SideStreams {
    cudaStream_t s1, s2;
    cudaEvent_t ev[8];
    SideStreams() {
        cudaStreamCreateWithFlags(&s1, cudaStreamNonBlocking);
        cudaStreamCreateWithFlags(&s2, cudaStreamNonBlocking);
        for (int i = 0; i < 8; i++) cudaEventCreateWithFlags(&ev[i], cudaEventDisableTiming);
    }
};
static SideStreams g_ss;

__device__ __forceinline__ float to_tf32(float x) {
    uint32_t u;
    asm("cvt.rna.tf32.f32 %0, %1;" : "=r"(u) : "f"(x));
    return __uint_as_float(u);
}

// ---------------- TF32 GEMM v2 (self terms): whole K in smem, 128x128 tile ----------------
#define GEMM_SMEM ((128 * 100 + 96 * 136) * 4)

__global__ void __launch_bounds__(256)
gemm_tf32_v2(const float* __restrict__ A, const float* __restrict__ W,
             const float* __restrict__ bias, float* __restrict__ Cm,
             int Nrows, int K, int M) {
    extern __shared__ float smem[];
    float (*As)[100] = reinterpret_cast<float(*)[100]>(smem);
    float (*Ws)[136] = reinterpret_cast<float(*)[136]>(smem + 128 * 100);

    int tid = threadIdx.x;
    int warp = tid >> 5, lane = tid & 31;
    int g = lane >> 2, t = lane & 3;
    int warpM = warp >> 2, warpN = warp & 3;
    int rb = warpM * 64, cb = warpN * 32;
    int row0 = blockIdx.y * 128, col0 = blockIdx.x * 128;

    int KA4 = K >> 2;
    for (int l = tid; l < 128 * KA4; l += 256) {
        int r = l / KA4;
        int q = (l - r * KA4) * 4;
        int gr = row0 + r;
        float4 av = (gr < Nrows) ? *(const float4*)(A + (size_t)gr * K + q)
                                 : make_float4(0.f, 0.f, 0.f, 0.f);
        av.x = to_tf32(av.x); av.y = to_tf32(av.y);
        av.z = to_tf32(av.z); av.w = to_tf32(av.w);
        *(float4*)(&As[r][q]) = av;
    }
    for (int l = tid; l < K * 32; l += 256) {
        int kk = l >> 5;
        int c4 = (l & 31) * 4;
        int gc = col0 + c4;
        float4 wv = (gc < M) ? *(const float4*)(W + (size_t)kk * M + gc)
                             : make_float4(0.f, 0.f, 0.f, 0.f);
        wv.x = to_tf32(wv.x); wv.y = to_tf32(wv.y);
        wv.z = to_tf32(wv.z); wv.w = to_tf32(wv.w);
        *(float4*)(&Ws[kk][c4]) = wv;
    }
    __syncthreads();

    float c[4][4][4];
#pragma unroll
    for (int i = 0; i < 4; i++)
#pragma unroll
        for (int j = 0; j < 4; j++)
#pragma unroll
            for (int q = 0; q < 4; q++) c[i][j][q] = 0.f;

    for (int kk = 0; kk < K; kk += 8) {
        uint32_t a[4][4];
#pragma unroll
        for (int i = 0; i < 4; i++) {
            int r = rb + i * 16 + g;
            a[i][0] = __float_as_uint(As[r][kk + t]);
            a[i][1] = __float_as_uint(As[r + 8][kk + t]);
            a[i][2] = __float_as_uint(As[r][kk + t + 4]);
            a[i][3] = __float_as_uint(As[r + 8][kk + t + 4]);
        }
        uint32_t b[4][2];
#pragma unroll
        for (int j = 0; j < 4; j++) {
            int cc = cb + j * 8 + g;
            b[j][0] = __float_as_uint(Ws[kk + t][cc]);
            b[j][1] = __float_as_uint(Ws[kk + t + 4][cc]);
        }
#pragma unroll
        for (int i = 0; i < 4; i++)
#pragma unroll
            for (int j = 0; j < 4; j++) {
                asm volatile(
                    "mma.sync.aligned.m16n8k8.row.col.f32.tf32.tf32.f32 "
                    "{%0,%1,%2,%3}, {%4,%5,%6,%7}, {%8,%9}, {%0,%1,%2,%3};"
                    : "+f"(c[i][j][0]), "+f"(c[i][j][1]),
                      "+f"(c[i][j][2]), "+f"(c[i][j][3])
                    : "r"(a[i][0]), "r"(a[i][1]), "r"(a[i][2]), "r"(a[i][3]),
                      "r"(b[j][0]), "r"(b[j][1]));
            }
    }

#pragma unroll
    for (int j = 0; j < 4; j++) {
        int gc = col0 + cb + j * 8 + 2 * t;
        if (gc >= M) continue;
        float b0 = bias[gc], b1 = bias[gc + 1];
#pragma unroll
        for (int i = 0; i < 4; i++) {
            int gr = row0 + rb + i * 16 + g;
            if (gr < Nrows)
                *(float2*)(Cm + (size_t)gr * M + gc) =
                    make_float2(c[i][j][0] + b0, c[i][j][1] + b1);
            if (gr + 8 < Nrows)
                *(float2*)(Cm + (size_t)(gr + 8) * M + gc) =
                    make_float2(c[i][j][2] + b0, c[i][j][3] + b1);
        }
    }
}

// ---------------- Y-GEMM: C[N,M] += Y[N,K](fp16) @ W2[K,M] + bavg; optional fp16 emit ------
// 64x128 tile, 256 threads = 8 warps (2x4), warp tile 32x32, K-chunk 32. K%32==0, M%4==0.
__global__ void __launch_bounds__(256)
gemm_y(const uint16_t* __restrict__ Y, int lda,
       const float* __restrict__ W2, const float* __restrict__ bavg,
       float* __restrict__ Cm, uint16_t* __restrict__ xhOut,
       int Nrows, int K, int M) {
    __shared__ float As[64][36];
    __shared__ float Ws[32][136];

    int tid = threadIdx.x;
    int warp = tid >> 5, lane = tid & 31;
    int g = lane >> 2, t = lane & 3;
    int warpM = warp >> 2, warpN = warp & 3;
    int rb = warpM * 32, cb = warpN * 32;
    int row0 = blockIdx.y * 64;

    int ar = tid >> 2;           // 0..63
    int aq = (tid & 3) * 8;      // 0,8,16,24

    float c[2][4][4];
#pragma unroll
    for (int i = 0; i < 2; i++)
#pragma unroll
        for (int j = 0; j < 4; j++)
#pragma unroll
            for (int q = 0; q < 4; q++) c[i][j][q] = 0.f;

    for (int k0 = 0; k0 < K; k0 += 32) {
        {
            int gr = row0 + ar;
            uint4 av = (gr < Nrows) ? *(const uint4*)(Y + (size_t)gr * lda + k0 + aq)
                                    : make_uint4(0u, 0u, 0u, 0u);
            const __half2* hp = (const __half2*)&av;
#pragma unroll
            for (int p = 0; p < 4; p++) {
                float2 f = __half22float2(hp[p]);
                As[ar][aq + 2 * p] = to_tf32(f.x);
                As[ar][aq + 2 * p + 1] = to_tf32(f.y);
            }
        }
#pragma unroll
        for (int i = 0; i < 4; i++) {
            int l = tid + i * 256;
            int kk = l >> 5;
            int c4 = (l & 31) * 4;
            float4 wv = (c4 < M) ? *(const float4*)(W2 + (size_t)(k0 + kk) * M + c4)
                                 : make_float4(0.f, 0.f, 0.f, 0.f);
            wv.x = to_tf32(wv.x); wv.y = to_tf32(wv.y);
            wv.z = to_tf32(wv.z); wv.w = to_tf32(wv.w);
            *(float4*)(&Ws[kk][c4]) = wv;
        }
        __syncthreads();

#pragma unroll
        for (int kk = 0; kk < 32; kk += 8) {
            uint32_t a[2][4];
#pragma unroll
            for (int i = 0; i < 2; i++) {
                int r = rb + i * 16 + g;
                a[i][0] = __float_as_uint(As[r][kk + t]);
                a[i][1] = __float_as_uint(As[r + 8][kk + t]);
                a[i][2] = __float_as_uint(As[r][kk + t + 4]);
                a[i][3] = __float_as_uint(As[r + 8][kk + t + 4]);
            }
            uint32_t b[4][2];
#pragma unroll
            for (int j = 0; j < 4; j++) {
                int cc = cb + j * 8 + g;
                b[j][0] = __float_as_uint(Ws[kk + t][cc]);
                b[j][1] = __float_as_uint(Ws[kk + t + 4][cc]);
            }
#pragma unroll
            for (int i = 0; i < 2; i++)
#pragma unroll
                for (int j = 0; j < 4; j++) {
                    asm volatile(
                        "mma.sync.aligned.m16n8k8.row.col.f32.tf32.tf32.f32 "
                        "{%0,%1,%2,%3}, {%4,%5,%6,%7}, {%8,%9}, {%0,%1,%2,%3};"
                        : "+f"(c[i][j][0]), "+f"(c[i][j][1]),
                          "+f"(c[i][j][2]), "+f"(c[i][j][3])
                        : "r"(a[i][0]), "r"(a[i][1]), "r"(a[i][2]), "r"(a[i][3]),
                          "r"(b[j][0]), "r"(b[j][1]));
                }
        }
        __syncthreads();
    }

#pragma unroll
    for (int j = 0; j < 4; j++) {
        int gc = cb + j * 8 + 2 * t;
        if (gc >= M) continue;
        float b0 = bavg[gc], b1 = bavg[gc + 1];
#pragma unroll
        for (int i = 0; i < 2; i++) {
            int gr = row0 + rb + i * 16 + g;
            if (gr < Nrows) {
                float2 old = *(float2*)(Cm + (size_t)gr * M + gc);
                float n0 = old.x + c[i][j][0] + b0;
                float n1 = old.y + c[i][j][1] + b1;
                *(float2*)(Cm + (size_t)gr * M + gc) = make_float2(n0, n1);
                if (xhOut) {
                    __half2 hv = __floats2half2_rn(n0, n1);
                    *(uint32_t*)(xhOut + (size_t)gr * M + gc) = *(uint32_t*)&hv;
                }
            }
            int gr8 = gr + 8;
            if (gr8 < Nrows) {
                float2 old = *(float2*)(Cm + (size_t)gr8 * M + gc);
                float n0 = old.x + c[i][j][2] + b0;
                float n1 = old.y + c[i][j][3] + b1;
                *(float2*)(Cm + (size_t)gr8 * M + gc) = make_float2(n0, n1);
                if (xhOut) {
                    __half2 hv = __floats2half2_rn(n0, n1);
                    *(uint32_t*)(xhOut + (size_t)gr8 * M + gc) = *(uint32_t*)&hv;
                }
            }
        }
    }
}

// ------- W2[(c_in*4+h)*C + c_out] = 0.25*Wm[c_in][h*C+c_out]; bavg; v projection -------
__global__ void permw2_kernel(const float* __restrict__ Wm, const float* __restrict__ bm,
                              const float* __restrict__ att,
                              float* __restrict__ W2, float* __restrict__ bavg,
                              float* __restrict__ v, int K, int C) {
    int idx = blockIdx.x * 256 + threadIdx.x;
    int M4 = 4 * C;
    if (idx < K * M4) {
        int row = idx / C, c_out = idx - row * C;
        int c_in = row >> 2, h = row & 3;
        W2[idx] = 0.25f * Wm[(size_t)c_in * M4 + h * C + c_out];
    }
    if (idx < C)
        bavg[idx] = 0.25f * (bm[idx] + bm[C + idx] + bm[2 * C + idx] + bm[3 * C + idx]);
    if (idx < (K + 1) * 4) {
        int k = idx >> 2, h = idx & 3;
        const float* base = (k < K) ? (Wm + (size_t)k * M4 + h * C) : (bm + h * C);
        const float* ar = att + h * C;
        float s = 0.f;
        for (int cc = 0; cc < C; cc++) s += base[cc] * ar[cc];
        v[idx] = s;
    }
}

// ---------------- fp32 -> fp16 convert (layer-1 input x) ----------------
__global__ void cvt_half_kernel(const float* __restrict__ in, uint16_t* __restrict__ out,
                                int total4) {
    int i = blockIdx.x * 256 + threadIdx.x;
    if (i >= total4) return;
    float4 f = ((const float4*)in)[i];
    __half2 a = __floats2half2_rn(f.x, f.y);
    __half2 b = __floats2half2_rn(f.z, f.w);
    uint2 pk = make_uint2(*(uint32_t*)&a, *(uint32_t*)&b);
    ((uint2*)out)[i] = pk;
}

// ---------------- ealpha[n,h] = exp(leakyrelu(x[n].v_h + c_h)) ----------------
__global__ void alpha_kernel(const float* __restrict__ x, const float* __restrict__ v,
                             float4* __restrict__ ealpha, int N, int K) {
    int gw = (blockIdx.x * blockDim.x + threadIdx.x) >> 5;
    int lane = threadIdx.x & 31;
    if (gw >= N) return;
    const float* xr = x + (size_t)gw * K;
    float s0 = 0.f, s1 = 0.f, s2 = 0.f, s3 = 0.f;
    for (int k = lane; k < K; k += 32) {
        float xv = xr[k];
        float4 vv = *(const float4*)(v + k * 4);
        s0 += xv * vv.x; s1 += xv * vv.y; s2 += xv * vv.z; s3 += xv * vv.w;
    }
#pragma unroll
    for (int off = 16; off >= 1; off >>= 1) {
        s0 += __shfl_xor_sync(0xffffffffu, s0, off);
        s1 += __shfl_xor_sync(0xffffffffu, s1, off);
        s2 += __shfl_xor_sync(0xffffffffu, s2, off);
        s3 += __shfl_xor_sync(0xffffffffu, s3, off);
    }
    if (lane == 0) {
        float4 cv = *(const float4*)(v + K * 4);
        float a0 = s0 + cv.x, a1 = s1 + cv.y, a2 = s2 + cv.z, a3 = s3 + cv.w;
        a0 = a0 > 0.f ? a0 : 0.2f * a0;
        a1 = a1 > 0.f ? a1 : 0.2f * a1;
        a2 = a2 > 0.f ? a2 : 0.2f * a2;
        a3 = a3 > 0.f ? a3 : 0.2f * a3;
        ealpha[gw] = make_float4(__expf(a0), __expf(a1), __expf(a2), __expf(a3));
    }
}

// ---------------- CSR build ----------------
__global__ void count_kernel(const int* __restrict__ dst, int* __restrict__ deg, int E) {
    int e = blockIdx.x * blockDim.x + threadIdx.x;
    if (e < E) atomicAdd(&deg[dst[e]], 1);
}
__global__ void scan1_kernel(const int* __restrict__ deg, int* __restrict__ rp,
                             int* __restrict__ partials, int N) {
    __shared__ int s[512];
    int tid = threadIdx.x;
    int i = blockIdx.x * 512 + tid;
    int v = (i < N) ? deg[i] : 0;
    s[tid] = v;
    __syncthreads();
#pragma unroll
    for (int off = 1; off < 512; off <<= 1) {
        int t = (tid >= off) ? s[tid - off] : 0;
        __syncthreads();
        s[tid] += t;
        __syncthreads();
    }
    if (i < N) rp[i] = s[tid] - v;
    if (tid == 511) partials[blockIdx.x] = s[511];
}
__global__ void scan_fix_kernel(int* __restrict__ rp, int* __restrict__ wrk,
                                const int* __restrict__ partials, int N, int E) {
    int b = blockIdx.x;
    int base = 0;
    for (int i = 0; i < b; i++) base += partials[i];
    int i = b * 512 + threadIdx.x;
    if (i < N) {
        int v = rp[i] + base;
        rp[i] = v;
        wrk[i] = v;
    }
    if (b == 0 && threadIdx.x == 0) rp[N] = E;
}
__global__ void scatter_kernel(const int* __restrict__ src, const int* __restrict__ dst,
                               int* __restrict__ wrk, int* __restrict__ colsrc, int E) {
    int e = blockIdx.x * blockDim.x + threadIdx.x;
    if (e >= E) return;
    int pos = atomicAdd(&wrk[dst[e]], 1);
    colsrc[pos] = src[e];
}

// ---- CSR aggregate on RAW fp16 features: Y[d] = per-head softmax-weighted feature sums ----
// Y layout: halves at position c*4+h (c = input channel, h = head). KIN = 64 or 96.
template<int KIN>
__global__ void csr_aggx_kernel(const int* __restrict__ rp, const int* __restrict__ cs,
                                const float4* __restrict__ ealpha,
                                const uint16_t* __restrict__ xh,
                                uint16_t* __restrict__ Y, int N) {
    int w = (blockIdx.x * blockDim.x + threadIdx.x) >> 5;
    int lane = threadIdx.x & 31;
    if (w >= N) return;
    int start = __ldg(&rp[w]);
    int end = __ldg(&rp[w + 1]);
    float d0 = 0.f, d1 = 0.f, d2 = 0.f, d3 = 0.f;

    if constexpr (KIN == 64) {
        float n0[4] = {0.f, 0.f, 0.f, 0.f};
        float n1[4] = {0.f, 0.f, 0.f, 0.f};
        for (int i = start; i < end; i++) {
            int s = __ldg(&cs[i]);
            float4 ea = __ldg(&ealpha[s]);
            d0 += ea.x; d1 += ea.y; d2 += ea.z; d3 += ea.w;
            uint32_t xv = __ldg((const uint32_t*)(xh + (size_t)s * 64) + lane);
            float2 f = __half22float2(*(__half2*)&xv);
            n0[0] += ea.x * f.x; n0[1] += ea.y * f.x; n0[2] += ea.z * f.x; n0[3] += ea.w * f.x;
            n1[0] += ea.x * f.y; n1[1] += ea.y * f.y; n1[2] += ea.z * f.y; n1[3] += ea.w * f.y;
        }
        float i0 = 1.f / (d0 + 1e-16f), i1 = 1.f / (d1 + 1e-16f);
        float i2 = 1.f / (d2 + 1e-16f), i3 = 1.f / (d3 + 1e-16f);
        __half2 o0 = __floats2half2_rn(n0[0] * i0, n0[1] * i1);
        __half2 o1 = __floats2half2_rn(n0[2] * i2, n0[3] * i3);
        __half2 o2 = __floats2half2_rn(n1[0] * i0, n1[1] * i1);
        __half2 o3 = __floats2half2_rn(n1[2] * i2, n1[3] * i3);
        uint4 pk = make_uint4(*(uint32_t*)&o0, *(uint32_t*)&o1,
                              *(uint32_t*)&o2, *(uint32_t*)&o3);
        ((uint4*)(Y + (size_t)w * 256))[lane] = pk;
    } else {
        float num[3][4];
#pragma unroll
        for (int cc = 0; cc < 3; cc++)
#pragma unroll
            for (int h = 0; h < 4; h++) num[cc][h] = 0.f;
        for (int i = start; i < end; i++) {
            int s = __ldg(&cs[i]);
            float4 ea = __ldg(&ealpha[s]);
            d0 += ea.x; d1 += ea.y; d2 += ea.z; d3 += ea.w;
            const __half* xr = (const __half*)xh + (size_t)s * 96 + lane;
#pragma unroll
            for (int cc = 0; cc < 3; cc++) {
                float f = __half2float(__ldg(xr + cc * 32));
                num[cc][0] += ea.x * f; num[cc][1] += ea.y * f;
                num[cc][2] += ea.z * f; num[cc][3] += ea.w * f;
            }
        }
        float i0 = 1.f / (d0 + 1e-16f), i1 = 1.f / (d1 + 1e-16f);
        float i2 = 1.f / (d2 + 1e-16f), i3 = 1.f / (d3 + 1e-16f);
#pragma unroll
        for (int cc = 0; cc < 3; cc++) {
            __half2 a = __floats2half2_rn(num[cc][0] * i0, num[cc][1] * i1);
            __half2 b = __floats2half2_rn(num[cc][2] * i2, num[cc][3] * i3);
            uint2 pk = make_uint2(*(uint32_t*)&a, *(uint32_t*)&b);
            ((uint2*)(Y + (size_t)w * 384))[lane + cc * 32] = pk;
        }
    }
}

// ---------------- global mean pool ----------------
__global__ void pool_kernel(const float* __restrict__ h, const int* __restrict__ batch,
                            float* __restrict__ pooled, int N) {
    int g = blockIdx.x;
    int lo = 0, hi = N;
    while (lo < hi) { int mid = (lo + hi) >> 1; if (batch[mid] < g) lo = mid + 1; else hi = mid; }
    int start = lo;
    lo = start; hi = N;
    while (lo < hi) { int mid = (lo + hi) >> 1; if (batch[mid] < g + 1) lo = mid + 1; else hi = mid; }
    int end = lo;
    int t = threadIdx.x;
    int c = t & 63, chunk = t >> 6;
    float acc = 0.f;
    for (int n = start + chunk; n < end; n += 4) acc += h[(size_t)n * 64 + c];
    __shared__ float sh[4][64];
    sh[chunk][c] = acc;
    __syncthreads();
    if (chunk == 0) {
        float s = sh[0][c] + sh[1][c] + sh[2][c] + sh[3][c];
        int cnt = end - start;
        pooled[g * 64 + c] = s / (float)(cnt > 0 ? cnt : 1);
    }
}

// ---------------- classifier + log_softmax ----------------
__global__ void fc_kernel(const float* __restrict__ pooled, const float* __restrict__ Wfc,
                          const float* __restrict__ bfc, float* __restrict__ out) {
    __shared__ float logits[GG][10];
    int t = threadIdx.x;
    if (t < GG * 10) {
        int g = t / 10, o = t % 10;
        float s = bfc[o];
        const float* pr = pooled + g * 64;
        for (int k = 0; k < 64; k++) s += pr[k] * Wfc[k * 10 + o];
        logits[g][o] = s;
    }
    __syncthreads();
    if (t < GG) {
        float mx = -1e30f;
        for (int o = 0; o < 10; o++) mx = fmaxf(mx, logits[t][o]);
        float sum = 0.f;
        for (int o = 0; o < 10; o++) sum += __expf(logits[t][o] - mx);
        float lse = mx + __logf(sum);
        for (int o = 0; o < 10; o++) out[t * 10 + o] = logits[t][o] - lse;
    }
}

// ---------------- launcher ----------------
extern "C" void kernel_launch(void* const* d_in, const int* in_sizes, int n_in,
                              void* d_out, int out_size) {
    const float* x    = (const float*)d_in[0];
    const int*   ei   = (const int*)d_in[1];
    const int*   batch= (const int*)d_in[2];
    const float* Wm1  = (const float*)d_in[3];
    const float* bm1  = (const float*)d_in[4];
    const float* att1 = (const float*)d_in[5];
    const float* Ws1  = (const float*)d_in[6];
    const float* bs1  = (const float*)d_in[7];
    const float* Wm2  = (const float*)d_in[8];
    const float* bm2  = (const float*)d_in[9];
    const float* att2 = (const float*)d_in[10];
    const float* Wm3  = (const float*)d_in[11];
    const float* bm3  = (const float*)d_in[12];
    const float* att3 = (const float*)d_in[13];
    const float* Ws3  = (const float*)d_in[14];
    const float* bs3  = (const float*)d_in[15];
    const float* Wfc  = (const float*)d_in[16];
    const float* bfc  = (const float*)d_in[17];
    float* out = (float*)d_out;

    const int N = NN;
    const int E = in_sizes[1] / 2;
    const int* src = ei;
    const int* dst = ei + E;

    uint16_t *p_Y, *p_xh; float4 *p_B4, *p_C4, *p_ea;
    float *p_pl, *p_v, *p_W2, *p_bavg;
    int *p_deg, *p_rp, *p_wrk, *p_cs, *p_part;
    cudaGetSymbolAddress((void**)&p_Y, g_Y);
    cudaGetSymbolAddress((void**)&p_xh, g_xh);
    cudaGetSymbolAddress((void**)&p_B4, g_B4);
    cudaGetSymbolAddress((void**)&p_C4, g_C4);
    cudaGetSymbolAddress((void**)&p_ea, g_ealpha);
    cudaGetSymbolAddress((void**)&p_pl, g_pooled);
    cudaGetSymbolAddress((void**)&p_v, g_v);
    cudaGetSymbolAddress((void**)&p_W2, g_W2);
    cudaGetSymbolAddress((void**)&p_bavg, g_bavg);
    cudaGetSymbolAddress((void**)&p_deg, g_deg);
    cudaGetSymbolAddress((void**)&p_rp, g_rowptr);
    cudaGetSymbolAddress((void**)&p_wrk, g_wrk);
    cudaGetSymbolAddress((void**)&p_cs, g_colsrc);
    cudaGetSymbolAddress((void**)&p_part, g_partials);
    float* p_B = (float*)p_B4;
    float* p_C = (float*)p_C4;
    float *v1 = p_v, *v2 = p_v + 404, *v3 = p_v + 808;
    float *W2_1 = p_W2, *W2_2 = p_W2 + 384 * 96, *W2_3 = p_W2 + 2 * 384 * 96;
    float *ba1 = p_bavg, *ba2 = p_bavg + 96, *ba3 = p_bavg + 192;

    cudaFuncSetAttribute(gemm_tf32_v2,
                         cudaFuncAttributeMaxDynamicSharedMemorySize, GEMM_SMEM);

    const int rowTiles128 = (N + 127) / 128;   // v2 self GEMMs
    const int rowTiles64  = (N + 63) / 64;     // Y-GEMM
    const int alphaBlocks = (N * 32 + 255) / 256;
    const int eBlocks = (E + 255) / 256;
    const int scanBlocks = (N + 511) / 512;
    const int aggBlocks = (N * 32 + 255) / 256;

    cudaStream_t s1 = g_ss.s1, s2 = g_ss.s2;
    cudaEvent_t* ev = g_ss.ev;

    // ================= fork =================
    cudaEventRecord(ev[0], 0);
    cudaStreamWaitEvent(s1, ev[0], 0);
    cudaStreamWaitEvent(s2, ev[0], 0);

    // s1: CSR build
    cudaMemsetAsync(p_deg, 0, N * sizeof(int), s1);
    count_kernel<<<eBlocks, 256, 0, s1>>>(dst, p_deg, E);
    scan1_kernel<<<scanBlocks, 512, 0, s1>>>(p_deg, p_rp, p_part, N);
    scan_fix_kernel<<<scanBlocks, 512, 0, s1>>>(p_rp, p_wrk, p_part, N, E);
    scatter_kernel<<<eBlocks, 256, 0, s1>>>(src, dst, p_wrk, p_cs, E);
    cudaEventRecord(ev[1], s1);

    // s2: L1 weight prep + x->fp16 + alpha1 + self-GEMM1
    permw2_kernel<<<(64 * 384 + 255) / 256, 256, 0, s2>>>(Wm1, bm1, att1, W2_1, ba1, v1, 64, 96);
    cvt_half_kernel<<<(N * 64 / 4 + 255) / 256, 256, 0, s2>>>(x, p_xh, N * 64 / 4);
    alpha_kernel<<<alphaBlocks, 256, 0, s2>>>(x, v1, p_ea, N, 64);
    gemm_tf32_v2<<<dim3(1, rowTiles128), 256, GEMM_SMEM, s2>>>(x, Ws1, bs1, p_B, N, 64, 96);
    cudaEventRecord(ev[2], s2);

    // main: L2/L3 weight prep
    permw2_kernel<<<(96 * 384 + 255) / 256, 256>>>(Wm2, bm2, att2, W2_2, ba2, v2, 96, 96);
    permw2_kernel<<<(96 * 256 + 255) / 256, 256>>>(Wm3, bm3, att3, W2_3, ba3, v3, 96, 64);

    // ================= Layer 1 =================
    cudaStreamWaitEvent(0, ev[1], 0);   // CSR ready
    cudaStreamWaitEvent(0, ev[2], 0);   // xh, ealpha1, self-term ready
    csr_aggx_kernel<64><<<aggBlocks, 256>>>(p_rp, p_cs, p_ea, p_xh, p_Y, N);
    gemm_y<<<dim3(1, rowTiles64), 256>>>(p_Y, 256, W2_1, ba1, p_B, p_xh, N, 256, 96);

    // ================= Layer 2 (self = identity; accumulate in place) =================
    alpha_kernel<<<alphaBlocks, 256>>>(p_B, v2, p_ea, N, 96);
    csr_aggx_kernel<96><<<aggBlocks, 256>>>(p_rp, p_cs, p_ea, p_xh, p_Y, N);
    gemm_y<<<dim3(1, rowTiles64), 256>>>(p_Y, 384, W2_2, ba2, p_B, p_xh, N, 384, 96);
    cudaEventRecord(ev[3], 0);

    // ================= Layer 3 =================
    // s1: self-GEMM3 overlaps alpha3 + agg3
    cudaStreamWaitEvent(s1, ev[3], 0);
    gemm_tf32_v2<<<dim3(1, rowTiles128), 256, GEMM_SMEM, s1>>>(p_B, Ws3, bs3, p_C, N, 96, 64);
    cudaEventRecord(ev[4], s1);

    alpha_kernel<<<alphaBlocks, 256>>>(p_B, v3, p_ea, N, 96);
    csr_aggx_kernel<96><<<aggBlocks, 256>>>(p_rp, p_cs, p_ea, p_xh, p_Y, N);
    cudaStreamWaitEvent(0, ev[4], 0);
    gemm_y<<<dim3(1, rowTiles64), 256>>>(p_Y, 384, W2_3, ba3, p_C, (uint16_t*)nullptr, N, 384, 64);

    // ---------- pool + classifier ----------
    pool_kernel<<<GG, 256>>>(p_C, batch, p_pl, N);
    fc_kernel<<<1, 640>>>(p_pl, Wfc, bfc, out);
}

// round 16
// speedup vs baseline: 1.1760x; 1.1760x over previous
#include <cuda_runtime.h>
#include <cuda_fp16.h>
#include <math.h>
#include <stdint.h>

#define NN 50000
#define EE 400000
#define GG 64

// ---------------- scratch ----------------
__device__ uint16_t g_xWh[NN * 384];   // half messages, layout [n][c][h] interleaved
__device__ float4   g_B4[NN * 24];     // N x 96 features
__device__ float4   g_C4[NN * 24];     // N x 96 / N x 64
__device__ float4   g_ealpha[NN];
__device__ float    g_v[3][404];       // per-layer projected attention vectors
__device__ float    g_pooled[GG * 64];
__device__ float    g_Wp[3][96 * 384]; // per-layer permuted weights
__device__ float    g_bp[3][384];      // per-layer permuted bias
__device__ int      g_deg[NN];
__device__ int      g_rowptr[NN + 1];
__device__ int      g_wrk[NN];
__device__ int      g_colsrc[EE];
__device__ int      g_partials[128];

// side streams + events, created once at load (no device memory involved)
struct SideStreams {
    cudaStream_t s1, s2;
    cudaEvent_t ev[12];
    SideStreams() {
        cudaStreamCreateWithFlags(&s1, cudaStreamNonBlocking);
        cudaStreamCreateWithFlags(&s2, cudaStreamNonBlocking);
        for (int i = 0; i < 12; i++) cudaEventCreateWithFlags(&ev[i], cudaEventDisableTiming);
    }
};
static SideStreams g_ss;

__device__ __forceinline__ float to_tf32(float x) {
    uint32_t u;
    asm("cvt.rna.tf32.f32 %0, %1;" : "=r"(u) : "f"(x));
    return __uint_as_float(u);
}

// ---------------- TF32 GEMM v2: whole K in smem, 128x128 tile, one sync ----------------
#define GEMM_SMEM ((128 * 100 + 96 * 136) * 4)

template<typename OutT>
__global__ void __launch_bounds__(256)
gemm_tf32_v2(const float* __restrict__ A, const float* __restrict__ W,
             const float* __restrict__ bias, OutT* __restrict__ Cm,
             int Nrows, int K, int M) {
    extern __shared__ float smem[];
    float (*As)[100] = reinterpret_cast<float(*)[100]>(smem);
    float (*Ws)[136] = reinterpret_cast<float(*)[136]>(smem + 128 * 100);

    int tid = threadIdx.x;
    int warp = tid >> 5, lane = tid & 31;
    int g = lane >> 2, t = lane & 3;
    int warpM = warp >> 2, warpN = warp & 3;
    int rb = warpM * 64, cb = warpN * 32;
    int row0 = blockIdx.y * 128, col0 = blockIdx.x * 128;

    int KA4 = K >> 2;
    for (int l = tid; l < 128 * KA4; l += 256) {
        int r = l / KA4;
        int q = (l - r * KA4) * 4;
        int gr = row0 + r;
        float4 av = (gr < Nrows) ? *(const float4*)(A + (size_t)gr * K + q)
                                 : make_float4(0.f, 0.f, 0.f, 0.f);
        av.x = to_tf32(av.x); av.y = to_tf32(av.y);
        av.z = to_tf32(av.z); av.w = to_tf32(av.w);
        *(float4*)(&As[r][q]) = av;
    }
    for (int l = tid; l < K * 32; l += 256) {
        int kk = l >> 5;
        int c4 = (l & 31) * 4;
        int gc = col0 + c4;
        float4 wv = (gc < M) ? *(const float4*)(W + (size_t)kk * M + gc)
                             : make_float4(0.f, 0.f, 0.f, 0.f);
        wv.x = to_tf32(wv.x); wv.y = to_tf32(wv.y);
        wv.z = to_tf32(wv.z); wv.w = to_tf32(wv.w);
        *(float4*)(&Ws[kk][c4]) = wv;
    }
    __syncthreads();

    float c[4][4][4];
#pragma unroll
    for (int i = 0; i < 4; i++)
#pragma unroll
        for (int j = 0; j < 4; j++)
#pragma unroll
            for (int q = 0; q < 4; q++) c[i][j][q] = 0.f;

    for (int kk = 0; kk < K; kk += 8) {
        uint32_t a[4][4];
#pragma unroll
        for (int i = 0; i < 4; i++) {
            int r = rb + i * 16 + g;
            a[i][0] = __float_as_uint(As[r][kk + t]);
            a[i][1] = __float_as_uint(As[r + 8][kk + t]);
            a[i][2] = __float_as_uint(As[r][kk + t + 4]);
            a[i][3] = __float_as_uint(As[r + 8][kk + t + 4]);
        }
        uint32_t b[4][2];
#pragma unroll
        for (int j = 0; j < 4; j++) {
            int cc = cb + j * 8 + g;
            b[j][0] = __float_as_uint(Ws[kk + t][cc]);
            b[j][1] = __float_as_uint(Ws[kk + t + 4][cc]);
        }
#pragma unroll
        for (int i = 0; i < 4; i++)
#pragma unroll
            for (int j = 0; j < 4; j++) {
                asm volatile(
                    "mma.sync.aligned.m16n8k8.row.col.f32.tf32.tf32.f32 "
                    "{%0,%1,%2,%3}, {%4,%5,%6,%7}, {%8,%9}, {%0,%1,%2,%3};"
                    : "+f"(c[i][j][0]), "+f"(c[i][j][1]),
                      "+f"(c[i][j][2]), "+f"(c[i][j][3])
                    : "r"(a[i][0]), "r"(a[i][1]), "r"(a[i][2]), "r"(a[i][3]),
                      "r"(b[j][0]), "r"(b[j][1]));
            }
    }

    constexpr bool HALF_OUT = (sizeof(OutT) == 2);
#pragma unroll
    for (int j = 0; j < 4; j++) {
        int gc = col0 + cb + j * 8 + 2 * t;
        if (gc >= M) continue;
        float b0 = bias[gc], b1 = bias[gc + 1];
#pragma unroll
        for (int i = 0; i < 4; i++) {
            int gr = row0 + rb + i * 16 + g;
            if (gr < Nrows) {
                if (HALF_OUT) {
                    __half2 hv = __floats2half2_rn(c[i][j][0] + b0, c[i][j][1] + b1);
                    *(__half2*)((uint16_t*)Cm + (size_t)gr * M + gc) = hv;
                } else {
                    *(float2*)((float*)Cm + (size_t)gr * M + gc) =
                        make_float2(c[i][j][0] + b0, c[i][j][1] + b1);
                }
            }
            if (gr + 8 < Nrows) {
                if (HALF_OUT) {
                    __half2 hv = __floats2half2_rn(c[i][j][2] + b0, c[i][j][3] + b1);
                    *(__half2*)((uint16_t*)Cm + (size_t)(gr + 8) * M + gc) = hv;
                } else {
                    *(float2*)((float*)Cm + (size_t)(gr + 8) * M + gc) =
                        make_float2(c[i][j][2] + b0, c[i][j][3] + b1);
                }
            }
        }
    }
}

// ------- fused: permute W columns (Wp[k][c*4+h] = Wm[k][h*C+c], bias likewise) + proj v -------
__global__ void permw_proj_kernel(const float* __restrict__ Wm, const float* __restrict__ bm,
                                  const float* __restrict__ att,
                                  float* __restrict__ Wp, float* __restrict__ bp,
                                  float* __restrict__ v, int K, int C) {
    int idx = blockIdx.x * 256 + threadIdx.x;
    int M = 4 * C;
    if (idx < K * M) {
        int k = idx / M, p = idx - k * M;
        Wp[idx] = Wm[(size_t)k * M + (p & 3) * C + (p >> 2)];
    }
    if (idx < M) bp[idx] = bm[(idx & 3) * C + (idx >> 2)];
    if (idx < (K + 1) * 4) {
        int k = idx >> 2, h = idx & 3;
        const float* base = (k < K) ? (Wm + (size_t)k * M + h * C) : (bm + h * C);
        const float* ar = att + h * C;
        float s = 0.f;
        for (int c = 0; c < C; c++) s += base[c] * ar[c];
        v[idx] = s;
    }
}

// ---------------- ealpha[n,h] = exp(leakyrelu(x[n].v_h + c_h)) ----------------
__global__ void alpha_kernel(const float* __restrict__ x, const float* __restrict__ v,
                             float4* __restrict__ ealpha, int N, int K) {
    int gw = (blockIdx.x * blockDim.x + threadIdx.x) >> 5;
    int lane = threadIdx.x & 31;
    if (gw >= N) return;
    const float* xr = x + (size_t)gw * K;
    float s0 = 0.f, s1 = 0.f, s2 = 0.f, s3 = 0.f;
    for (int k = lane; k < K; k += 32) {
        float xv = xr[k];
        float4 vv = *(const float4*)(v + k * 4);
        s0 += xv * vv.x; s1 += xv * vv.y; s2 += xv * vv.z; s3 += xv * vv.w;
    }
#pragma unroll
    for (int off = 16; off >= 1; off >>= 1) {
        s0 += __shfl_xor_sync(0xffffffffu, s0, off);
        s1 += __shfl_xor_sync(0xffffffffu, s1, off);
        s2 += __shfl_xor_sync(0xffffffffu, s2, off);
        s3 += __shfl_xor_sync(0xffffffffu, s3, off);
    }
    if (lane == 0) {
        float4 cv = *(const float4*)(v + K * 4);
        float a0 = s0 + cv.x, a1 = s1 + cv.y, a2 = s2 + cv.z, a3 = s3 + cv.w;
        a0 = a0 > 0.f ? a0 : 0.2f * a0;
        a1 = a1 > 0.f ? a1 : 0.2f * a1;
        a2 = a2 > 0.f ? a2 : 0.2f * a2;
        a3 = a3 > 0.f ? a3 : 0.2f * a3;
        ealpha[gw] = make_float4(__expf(a0), __expf(a1), __expf(a2), __expf(a3));
    }
}

// ---------------- CSR build ----------------
__global__ void count_kernel(const int* __restrict__ dst, int* __restrict__ deg, int E) {
    int e = blockIdx.x * blockDim.x + threadIdx.x;
    if (e < E) atomicAdd(&deg[dst[e]], 1);
}
__global__ void scan1_kernel(const int* __restrict__ deg, int* __restrict__ rp,
                             int* __restrict__ partials, int N) {
    __shared__ int s[512];
    int tid = threadIdx.x;
    int i = blockIdx.x * 512 + tid;
    int v = (i < N) ? deg[i] : 0;
    s[tid] = v;
    __syncthreads();
#pragma unroll
    for (int off = 1; off < 512; off <<= 1) {
        int t = (tid >= off) ? s[tid - off] : 0;
        __syncthreads();
        s[tid] += t;
        __syncthreads();
    }
    if (i < N) rp[i] = s[tid] - v;
    if (tid == 511) partials[blockIdx.x] = s[511];
}
__global__ void scan_fix_kernel(int* __restrict__ rp, int* __restrict__ wrk,
                                const int* __restrict__ partials, int N, int E) {
    int b = blockIdx.x;
    int base = 0;
    for (int i = 0; i < b; i++) base += partials[i];
    int i = b * 512 + threadIdx.x;
    if (i < N) {
        int v = rp[i] + base;
        rp[i] = v;
        wrk[i] = v;
    }
    if (b == 0 && threadIdx.x == 0) rp[N] = E;
}
__global__ void scatter_kernel(const int* __restrict__ src, const int* __restrict__ dst,
                               int* __restrict__ wrk, int* __restrict__ colsrc, int E) {
    int e = blockIdx.x * blockDim.x + threadIdx.x;
    if (e >= E) return;
    int pos = atomicAdd(&wrk[dst[e]], 1);
    colsrc[pos] = src[e];
}

// ---------------- CSR aggregate: warp per dst, softmax + head-mean fused -----------------
template<int C>
__global__ void csr_agg_kernel(const int* __restrict__ rp, const int* __restrict__ cs,
                               const float4* __restrict__ ealpha,
                               const uint16_t* __restrict__ xWh,
                               float* __restrict__ outF, int N) {
    constexpr int CPL = C / 32;
    int w = (blockIdx.x * blockDim.x + threadIdx.x) >> 5;
    int lane = threadIdx.x & 31;
    if (w >= N) return;
    int start = __ldg(&rp[w]);
    int end = __ldg(&rp[w + 1]);

    float num[CPL][4];
#pragma unroll
    for (int cc = 0; cc < CPL; cc++)
#pragma unroll
        for (int h = 0; h < 4; h++) num[cc][h] = 0.f;
    float d0 = 0.f, d1 = 0.f, d2 = 0.f, d3 = 0.f;

#pragma unroll 2
    for (int i = start; i < end; i++) {
        int s = __ldg(&cs[i]);
        float4 ea = __ldg(&ealpha[s]);
        d0 += ea.x; d1 += ea.y; d2 += ea.z; d3 += ea.w;
        const uint2* m = (const uint2*)(xWh + (size_t)s * C * 4);
#pragma unroll
        for (int cc = 0; cc < CPL; cc++) {
            uint2 v = __ldg(&m[lane + cc * 32]);
            __half2 p0 = *(__half2*)&v.x;
            __half2 p1 = *(__half2*)&v.y;
            float2 f0 = __half22float2(p0);
            float2 f1 = __half22float2(p1);
            num[cc][0] += ea.x * f0.x;
            num[cc][1] += ea.y * f0.y;
            num[cc][2] += ea.z * f1.x;
            num[cc][3] += ea.w * f1.y;
        }
    }
    float i0 = 0.25f / (d0 + 1e-16f);
    float i1 = 0.25f / (d1 + 1e-16f);
    float i2 = 0.25f / (d2 + 1e-16f);
    float i3 = 0.25f / (d3 + 1e-16f);
#pragma unroll
    for (int cc = 0; cc < CPL; cc++) {
        int c = lane + cc * 32;
        float* o = outF + (size_t)w * C + c;
        *o = *o + num[cc][0] * i0 + num[cc][1] * i1 + num[cc][2] * i2 + num[cc][3] * i3;
    }
}

// ---------------- global mean pool ----------------
__global__ void pool_kernel(const float* __restrict__ h, const int* __restrict__ batch,
                            float* __restrict__ pooled, int N) {
    int g = blockIdx.x;
    int lo = 0, hi = N;
    while (lo < hi) { int mid = (lo + hi) >> 1; if (batch[mid] < g) lo = mid + 1; else hi = mid; }
    int start = lo;
    lo = start; hi = N;
    while (lo < hi) { int mid = (lo + hi) >> 1; if (batch[mid] < g + 1) lo = mid + 1; else hi = mid; }
    int end = lo;
    int t = threadIdx.x;
    int c = t & 63, chunk = t >> 6;
    float acc = 0.f;
    for (int n = start + chunk; n < end; n += 4) acc += h[(size_t)n * 64 + c];
    __shared__ float sh[4][64];
    sh[chunk][c] = acc;
    __syncthreads();
    if (chunk == 0) {
        float s = sh[0][c] + sh[1][c] + sh[2][c] + sh[3][c];
        int cnt = end - start;
        pooled[g * 64 + c] = s / (float)(cnt > 0 ? cnt : 1);
    }
}

// ---------------- classifier + log_softmax ----------------
__global__ void fc_kernel(const float* __restrict__ pooled, const float* __restrict__ Wfc,
                          const float* __restrict__ bfc, float* __restrict__ out) {
    __shared__ float logits[GG][10];
    int t = threadIdx.x;
    if (t < GG * 10) {
        int g = t / 10, o = t % 10;
        float s = bfc[o];
        const float* pr = pooled + g * 64;
        for (int k = 0; k < 64; k++) s += pr[k] * Wfc[k * 10 + o];
        logits[g][o] = s;
    }
    __syncthreads();
    if (t < GG) {
        float mx = -1e30f;
        for (int o = 0; o < 10; o++) mx = fmaxf(mx, logits[t][o]);
        float sum = 0.f;
        for (int o = 0; o < 10; o++) sum += __expf(logits[t][o] - mx);
        float lse = mx + __logf(sum);
        for (int o = 0; o < 10; o++) out[t * 10 + o] = logits[t][o] - lse;
    }
}

// ---------------- launcher ----------------
extern "C" void kernel_launch(void* const* d_in, const int* in_sizes, int n_in,
                              void* d_out, int out_size) {
    const float* x    = (const float*)d_in[0];
    const int*   ei   = (const int*)d_in[1];
    const int*   batch= (const int*)d_in[2];
    const float* Wm1  = (const float*)d_in[3];
    const float* bm1  = (const float*)d_in[4];
    const float* att1 = (const float*)d_in[5];
    const float* Ws1  = (const float*)d_in[6];
    const float* bs1  = (const float*)d_in[7];
    const float* Wm2  = (const float*)d_in[8];
    const float* bm2  = (const float*)d_in[9];
    const float* att2 = (const float*)d_in[10];
    const float* Wm3  = (const float*)d_in[11];
    const float* bm3  = (const float*)d_in[12];
    const float* att3 = (const float*)d_in[13];
    const float* Ws3  = (const float*)d_in[14];
    const float* bs3  = (const float*)d_in[15];
    const float* Wfc  = (const float*)d_in[16];
    const float* bfc  = (const float*)d_in[17];
    float* out = (float*)d_out;

    const int N = NN;
    const int E = in_sizes[1] / 2;
    const int* src = ei;
    const int* dst = ei + E;

    uint16_t* p_xWh; float4 *p_B4, *p_C4, *p_ea;
    float *p_pl, *p_v, *p_Wp, *p_bp;
    int *p_deg, *p_rp, *p_wrk, *p_cs, *p_part;
    cudaGetSymbolAddress((void**)&p_xWh, g_xWh);
    cudaGetSymbolAddress((void**)&p_B4, g_B4);
    cudaGetSymbolAddress((void**)&p_C4, g_C4);
    cudaGetSymbolAddress((void**)&p_ea, g_ealpha);
    cudaGetSymbolAddress((void**)&p_pl, g_pooled);
    cudaGetSymbolAddress((void**)&p_v, g_v);
    cudaGetSymbolAddress((void**)&p_Wp, g_Wp);
    cudaGetSymbolAddress((void**)&p_bp, g_bp);
    cudaGetSymbolAddress((void**)&p_deg, g_deg);
    cudaGetSymbolAddress((void**)&p_rp, g_rowptr);
    cudaGetSymbolAddress((void**)&p_wrk, g_wrk);
    cudaGetSymbolAddress((void**)&p_cs, g_colsrc);
    cudaGetSymbolAddress((void**)&p_part, g_partials);
    float* p_B = (float*)p_B4;
    float* p_C = (float*)p_C4;
    float *v1 = p_v, *v2 = p_v + 404, *v3 = p_v + 808;
    float *Wp1 = p_Wp, *Wp2 = p_Wp + 96 * 384, *Wp3 = p_Wp + 2 * 96 * 384;
    float *bp1 = p_bp, *bp2 = p_bp + 384, *bp3 = p_bp + 768;

    cudaFuncSetAttribute(gemm_tf32_v2<uint16_t>,
                         cudaFuncAttributeMaxDynamicSharedMemorySize, GEMM_SMEM);
    cudaFuncSetAttribute(gemm_tf32_v2<float>,
                         cudaFuncAttributeMaxDynamicSharedMemorySize, GEMM_SMEM);

    const int rowTiles = (N + 127) / 128;            // 391
    const int alphaBlocks = (N * 32 + 255) / 256;
    const int eBlocks = (E + 255) / 256;
    const int scanBlocks = (N + 511) / 512;
    const int aggBlocks = (N * 32 + 255) / 256;

    cudaStream_t s1 = g_ss.s1, s2 = g_ss.s2;
    cudaEvent_t* ev = g_ss.ev;

    // ================= fork =================
    cudaEventRecord(ev[0], 0);
    cudaStreamWaitEvent(s1, ev[0], 0);
    cudaStreamWaitEvent(s2, ev[0], 0);

    // s1: CSR build, then L2/L3 weight prep (only needed at gemm2/gemm3, far later)
    cudaMemsetAsync(p_deg, 0, N * sizeof(int), s1);
    count_kernel<<<eBlocks, 256, 0, s1>>>(dst, p_deg, E);
    scan1_kernel<<<scanBlocks, 512, 0, s1>>>(p_deg, p_rp, p_part, N);
    scan_fix_kernel<<<scanBlocks, 512, 0, s1>>>(p_rp, p_wrk, p_part, N, E);
    scatter_kernel<<<eBlocks, 256, 0, s1>>>(src, dst, p_wrk, p_cs, E);
    cudaEventRecord(ev[1], s1);                       // CSR ready
    permw_proj_kernel<<<(96 * 384 + 255) / 256, 256, 0, s1>>>(Wm2, bm2, att2, Wp2, bp2, v2, 96, 96);
    permw_proj_kernel<<<(96 * 256 + 255) / 256, 256, 0, s1>>>(Wm3, bm3, att3, Wp3, bp3, v3, 96, 64);
    cudaEventRecord(ev[4], s1);                       // Wp2/v2/Wp3/v3 ready

    // s2: L1 weight prep (event immediately!), then alpha1 + self-GEMM1
    permw_proj_kernel<<<(64 * 384 + 255) / 256, 256, 0, s2>>>(Wm1, bm1, att1, Wp1, bp1, v1, 64, 96);
    cudaEventRecord(ev[2], s2);                       // Wp1/v1 ready
    alpha_kernel<<<alphaBlocks, 256, 0, s2>>>(x, v1, p_ea, N, 64);
    gemm_tf32_v2<float><<<dim3(1, rowTiles), 256, GEMM_SMEM, s2>>>(x, Ws1, bs1, p_B, N, 64, 96);
    cudaEventRecord(ev[3], s2);                       // ealpha1 + self-term ready

    // main: L1 msg GEMM starts as soon as Wp1 exists
    cudaStreamWaitEvent(0, ev[2], 0);
    gemm_tf32_v2<uint16_t><<<dim3(3, rowTiles), 256, GEMM_SMEM>>>(x, Wp1, bp1, p_xWh, N, 64, 384);
    cudaStreamWaitEvent(0, ev[1], 0);                 // CSR ready
    cudaStreamWaitEvent(0, ev[3], 0);                 // ealpha1 + self-term ready
    csr_agg_kernel<96><<<aggBlocks, 256>>>(p_rp, p_cs, p_ea, p_xWh, p_B, N);

    // ================= Layer 2 (alpha2 on s2 ∥ msg-GEMM2 on main) =================
    cudaEventRecord(ev[5], 0);                        // p_B (layer-1 out) ready
    cudaStreamWaitEvent(s2, ev[5], 0);
    alpha_kernel<<<alphaBlocks, 256, 0, s2>>>(p_B, v2, p_ea, N, 96);
    cudaEventRecord(ev[6], s2);
    cudaStreamWaitEvent(0, ev[4], 0);                 // Wp2 ready (long since done)
    gemm_tf32_v2<uint16_t><<<dim3(3, rowTiles), 256, GEMM_SMEM>>>(p_B, Wp2, bp2, p_xWh, N, 96, 384);
    cudaStreamWaitEvent(0, ev[6], 0);                 // alpha2 done before p_B overwritten
    csr_agg_kernel<96><<<aggBlocks, 256>>>(p_rp, p_cs, p_ea, p_xWh, p_B, N);

    // ================= Layer 3 (alpha3 on s2 ∥ self-GEMM3 on s1 ∥ msg-GEMM3 on main) ======
    cudaEventRecord(ev[7], 0);                        // p_B (layer-2 out) ready
    cudaStreamWaitEvent(s2, ev[7], 0);
    alpha_kernel<<<alphaBlocks, 256, 0, s2>>>(p_B, v3, p_ea, N, 96);
    cudaEventRecord(ev[8], s2);
    cudaStreamWaitEvent(s1, ev[7], 0);
    gemm_tf32_v2<float><<<dim3(1, rowTiles), 256, GEMM_SMEM, s1>>>(p_B, Ws3, bs3, p_C, N, 96, 64);
    cudaEventRecord(ev[9], s1);
    gemm_tf32_v2<uint16_t><<<dim3(2, rowTiles), 256, GEMM_SMEM>>>(p_B, Wp3, bp3, p_xWh, N, 96, 256);
    cudaStreamWaitEvent(0, ev[8], 0);
    cudaStreamWaitEvent(0, ev[9], 0);
    csr_agg_kernel<64><<<aggBlocks, 256>>>(p_rp, p_cs, p_ea, p_xWh, p_C, N);

    // ---------- pool + classifier ----------
    pool_kernel<<<GG, 256>>>(p_C, batch, p_pl, N);
    fc_kernel<<<1, 640>>>(p_pl, Wfc, bfc, out);
}